// round 12
// baseline (speedup 1.0000x reference)
#include <cuda_runtime.h>
#include <cuda_bf16.h>
#include <math.h>
#include <stdint.h>

#define T_TOK 8192
#define DIM   2048
#define IDIM  2048
#define NEXP  8
#define NPAIR 16384
#define NTMAX 136
#define KC    32
#define NKT   64
#define TBS   8192
#define SM12  (4*6*TBS)     // 192 KB
#define SM3   (3*4*TBS)     // 96 KB
#define EPAD  144

// ---------------- device scratch ----------------
__device__ int   g_expert[NPAIR];
__device__ float g_weight[NPAIR];
__device__ int   g_cnt[NEXP], g_cursor[NEXP];
__device__ int   g_pos[NPAIR];
__device__ int   g_tstart[NTMAX], g_texp[NTMAX], g_trows[NTMAX];
__device__ int   g_flag;
__device__ __align__(16) __nv_bfloat16 g_xph[(size_t)NPAIR*DIM];
__device__ __align__(16) __nv_bfloat16 g_xpl[(size_t)NPAIR*DIM];
__device__ __align__(16) __nv_bfloat16 g_w0h[(size_t)NEXP*DIM*IDIM];
__device__ __align__(16) __nv_bfloat16 g_w0l[(size_t)NEXP*DIM*IDIM];
__device__ __align__(16) __nv_bfloat16 g_w1h[(size_t)NEXP*DIM*IDIM];
__device__ __align__(16) __nv_bfloat16 g_w1l[(size_t)NEXP*DIM*IDIM];
__device__ __align__(16) __nv_bfloat16 g_woh[(size_t)NEXP*DIM*IDIM];
__device__ __align__(16) __nv_bfloat16 g_wol[(size_t)NEXP*DIM*IDIM];
__device__ __align__(16) __nv_bfloat16 g_ih[(size_t)NPAIR*IDIM];
__device__ __align__(16) __nv_bfloat16 g_il[(size_t)NPAIR*IDIM];
__device__ __align__(16) float g_op[(size_t)NPAIR*DIM];

// ---------------- helpers ----------------
__device__ __forceinline__ uint32_t s2u(const void* p) {
    uint32_t a;
    asm("{ .reg .u64 t; cvta.to.shared.u64 t, %1; cvt.u32.u64 %0, t; }" : "=r"(a) : "l"(p));
    return a;
}
__device__ __forceinline__ uint32_t sw64(uint32_t o) { return o ^ ((o >> 3) & 0x30); }

#define CP16(dst, src) asm volatile("cp.async.cg.shared.global [%0], [%1], 16;" \
                                    :: "r"(dst), "l"(src) : "memory")
#define CP_COMMIT() asm volatile("cp.async.commit_group;" ::: "memory")
#define CP_WAITN(n) asm volatile("cp.async.wait_group %0;" :: "n"(n) : "memory")

#define LDSM4(r0,r1,r2,r3,a) asm volatile( \
    "ldmatrix.sync.aligned.m8n8.x4.shared.b16 {%0,%1,%2,%3}, [%4];" \
    : "=r"(r0),"=r"(r1),"=r"(r2),"=r"(r3) : "r"(a))
#define MMA(cc, A, B) asm volatile( \
    "mma.sync.aligned.m16n8k16.row.col.f32.bf16.bf16.f32 " \
    "{%0,%1,%2,%3}, {%4,%5,%6,%7}, {%8,%9}, {%0,%1,%2,%3};" \
    : "+f"(cc[0]),"+f"(cc[1]),"+f"(cc[2]),"+f"(cc[3]) \
    : "r"(A[0]),"r"(A[1]),"r"(A[2]),"r"(A[3]),"r"(B[0]),"r"(B[1]))

// ---------------- router (own kernel, main stream) ----------------
__global__ void k_router(const float* __restrict__ logits) {
    int t = blockIdx.x * blockDim.x + threadIdx.x;
    const float* l = logits + t * NEXP;
    float v1 = -1e30f, v2 = -1e30f; int i1 = 0, i2 = 0;
#pragma unroll
    for (int e = 0; e < NEXP; ++e) {
        float v = l[e];
        if (v > v1)      { v2 = v1; i2 = i1; v1 = v; i1 = e; }
        else if (v > v2) { v2 = v;  i2 = e; }
    }
    float p = expf(v2 - v1);
    float sden = 1.0f + p;
    float w1 = 1.0f / sden, w2 = p / sden;
    float sn = w1 + w2; w1 /= sn; w2 /= sn;
    g_expert[2*t] = i1; g_expert[2*t+1] = i2;
    g_weight[2*t] = w1; g_weight[2*t+1] = w2;
    atomicAdd(&g_cnt[i1], 1);
    atomicAdd(&g_cnt[i2], 1);
}

// ---------------- weight conversion core: 64x64 tile, transpose + split -----
__device__ __forceinline__ void conv_tile(const float* __restrict__ W,
                                          __nv_bfloat16* __restrict__ Th,
                                          __nv_bfloat16* __restrict__ Tl,
                                          int e, int k0, int n0) {
    __shared__ float s[64][65];
    const float* src = W + (size_t)e * DIM * IDIM;
    const int tx = threadIdx.x & 63, ty = threadIdx.x >> 6;    // 64 x 4
#pragma unroll
    for (int i = 0; i < 16; ++i) {
        int row = ty + i * 4;
        s[row][tx] = src[(size_t)(k0 + row) * IDIM + n0 + tx];
    }
    __syncthreads();
    const int kp = (threadIdx.x & 31) * 2;
    const int nl = threadIdx.x >> 5;
#pragma unroll
    for (int pass = 0; pass < 8; ++pass) {
        int n_loc = nl + pass * 8;
        float x0 = s[kp][n_loc], x1 = s[kp + 1][n_loc];
        __nv_bfloat162 h = __floats2bfloat162_rn(x0, x1);
        __nv_bfloat162 l = __floats2bfloat162_rn(x0 - __bfloat162float(h.x),
                                                 x1 - __bfloat162float(h.y));
        size_t o = (size_t)e * DIM * IDIM + (size_t)(n0 + n_loc) * DIM + (k0 + kp);
        *(__nv_bfloat162*)(Th + o) = h;
        *(__nv_bfloat162*)(Tl + o) = l;
    }
}

// ---------------- conversion of wi0/wi1 (side stream, overlaps router+prep) -
__global__ void k_convw01(const float* __restrict__ W0, const float* __restrict__ W1) {
    int z = blockIdx.z;
    int wsel = z >> 3, e = z & 7;
    conv_tile(wsel ? W1 : W0, wsel ? g_w1h : g_w0h, wsel ? g_w1l : g_w0l,
              e, blockIdx.x * 64, blockIdx.y * 64);
}

// ---------------- conversion of wo (side stream, overlaps gemm12) -----------
__global__ void k_convwo(const float* __restrict__ WO) {
    conv_tile(WO, g_woh, g_wol, blockIdx.z, blockIdx.x * 64, blockIdx.y * 64);
}

// ---------------- prep: schedule + scatter + permute/split (per token) ------
__global__ void k_prep(const float* __restrict__ X) {
    __shared__ int s_d0, s_d1;
    if (blockIdx.x == 0 && threadIdx.x == 0) {
        int off = 0, nt = 0;
        for (int e = 0; e < NEXP; ++e) {
            int c = g_cnt[e];
            g_cursor[e] = off;
            for (int s = 0; s < c; s += 128) {
                g_tstart[nt] = off + s; g_texp[nt] = e;
                g_trows[nt] = (c - s < 128) ? (c - s) : 128; nt++;
            }
            off += c;
        }
        for (int i = nt; i < NTMAX; ++i) g_trows[i] = 0;
        __threadfence();
        atomicExch(&g_flag, 1);
    }
    const int t = blockIdx.x;
    if (threadIdx.x == 0) {
        while (atomicAdd(&g_flag, 0) == 0) {}
        int d0 = atomicAdd(&g_cursor[g_expert[2*t]],   1);
        int d1 = atomicAdd(&g_cursor[g_expert[2*t+1]], 1);
        g_pos[2*t] = d0; g_pos[2*t+1] = d1;
        s_d0 = d0; s_d1 = d1;
    }
    __syncthreads();
    const int d0 = s_d0, d1 = s_d1;
    const float4* src = (const float4*)(X + (size_t)t * DIM);
    __nv_bfloat162* dh0 = (__nv_bfloat162*)(g_xph + (size_t)d0 * DIM);
    __nv_bfloat162* dl0 = (__nv_bfloat162*)(g_xpl + (size_t)d0 * DIM);
    __nv_bfloat162* dh1 = (__nv_bfloat162*)(g_xph + (size_t)d1 * DIM);
    __nv_bfloat162* dl1 = (__nv_bfloat162*)(g_xpl + (size_t)d1 * DIM);
#pragma unroll
    for (int i = 0; i < 4; ++i) {
        int c = threadIdx.x + i * 128;
        float4 v = src[c];
        __nv_bfloat162 h0 = __floats2bfloat162_rn(v.x, v.y);
        __nv_bfloat162 h1 = __floats2bfloat162_rn(v.z, v.w);
        __nv_bfloat162 l0 = __floats2bfloat162_rn(v.x - __bfloat162float(h0.x),
                                                  v.y - __bfloat162float(h0.y));
        __nv_bfloat162 l1 = __floats2bfloat162_rn(v.z - __bfloat162float(h1.x),
                                                  v.w - __bfloat162float(h1.y));
        dh0[2*c] = h0; dh0[2*c+1] = h1;
        dl0[2*c] = l0; dl0[2*c+1] = l1;
        dh1[2*c] = h0; dh1[2*c+1] = h1;
        dl1[2*c] = l0; dl1[2*c+1] = l1;
    }
}

// ---------------- fused GEMM1+2, warp-specialized (512 threads) -------------
__global__ void __launch_bounds__(512, 1) k_gemm12() {
    extern __shared__ char smem[];
    const int tid = threadIdx.x, lane = tid & 31, wid = tid >> 5;
    const int grp = wid >> 3, gid = wid & 7;
    const int bx = blockIdx.x, by = blockIdx.y;
    const int rows = g_trows[bx];
    if (rows == 0) return;
    const int rs = g_tstart[bx], e = g_texp[bx];
    const uint32_t sb = s2u(smem);
    const size_t eo = (size_t)e * DIM * IDIM;

    const int lr = tid >> 2, lu = tid & 3;
    const uint32_t d0 = sw64(lr*64 + lu*16);
    int ar = rs + lr; if (ar >= NPAIR) ar = NPAIR - 1;
    const __nv_bfloat16* pxh = g_xph + (size_t)ar*2048 + lu*8;
    const __nv_bfloat16* pxl = g_xpl + (size_t)ar*2048 + lu*8;
    const size_t bofs = (size_t)(by*128 + lr)*2048 + lu*8;
    const __nv_bfloat16* p0h = g_w0h + eo + bofs;
    const __nv_bfloat16* p0l = g_w0l + eo + bofs;
    const __nv_bfloat16* p1h = g_w1h + eo + bofs;
    const __nv_bfloat16* p1l = g_w1l + eo + bofs;

#define ISSUE12(kt) { uint32_t st = sb + ((kt) & 3)*6*TBS; size_t k0 = (size_t)(kt)*KC; \
        CP16(st         + d0, pxh + k0); CP16(st +   TBS + d0, pxl + k0); \
        CP16(st + 2*TBS + d0, p0h + k0); CP16(st + 3*TBS + d0, p0l + k0); \
        CP16(st + 4*TBS + d0, p1h + k0); CP16(st + 5*TBS + d0, p1l + k0); }

    const int wm = gid & 1, wn = gid >> 1;
    const uint32_t a_row = wm*64 + (lane & 15);
    const uint32_t a_kb  = ((lane >> 4) & 1) * 16;
    const uint32_t b_row = wn*32 + ((lane >> 4) & 1)*8 + (lane & 7);
    const uint32_t b_k16 = ((lane >> 3) & 1) * 16;
    const uint32_t bh_tile = (2 + 2*grp)*TBS;
    const uint32_t bl_tile = (3 + 2*grp)*TBS;

    float c[4][4][4];
#pragma unroll
    for (int m = 0; m < 4; ++m)
#pragma unroll
        for (int n = 0; n < 4; ++n)
#pragma unroll
            for (int q = 0; q < 4; ++q) c[m][n][q] = 0.f;

    ISSUE12(0); CP_COMMIT();
    ISSUE12(1); CP_COMMIT();
    ISSUE12(2); CP_COMMIT();

    for (int kt = 0; kt < NKT; ++kt) {
        CP_WAITN(2);
        __syncthreads();
        if (kt + 3 < NKT) ISSUE12(kt + 3);
        CP_COMMIT();
        const uint32_t st = sb + (kt & 3)*6*TBS;
#pragma unroll
        for (int kk = 0; kk < 2; ++kk) {
            const uint32_t kb = kk * 32;
            uint32_t fh[4][2], fl[4][2];
#pragma unroll
            for (int p = 0; p < 2; ++p) {
                uint32_t bo = sw64((b_row + p*16)*64 + kb + b_k16);
                LDSM4(fh[2*p][0], fh[2*p][1], fh[2*p+1][0], fh[2*p+1][1], st + bh_tile + bo);
                LDSM4(fl[2*p][0], fl[2*p][1], fl[2*p+1][0], fl[2*p+1][1], st + bl_tile + bo);
            }
#pragma unroll
            for (int m = 0; m < 4; ++m) {
                uint32_t ao = sw64((a_row + m*16)*64 + kb + a_kb);
                uint32_t ah[4], al[4];
                LDSM4(ah[0], ah[1], ah[2], ah[3], st + ao);
                LDSM4(al[0], al[1], al[2], al[3], st + TBS + ao);
#pragma unroll
                for (int n = 0; n < 4; ++n) MMA(c[m][n], ah, fh[n]);
#pragma unroll
                for (int n = 0; n < 4; ++n) MMA(c[m][n], ah, fl[n]);
#pragma unroll
                for (int n = 0; n < 4; ++n) MMA(c[m][n], al, fh[n]);
            }
        }
    }
#undef ISSUE12

    __syncthreads();
    float* hs = (float*)smem;
    float* mydst = hs + (size_t)grp * 128 * EPAD;
    const int rbase = wm*64 + (lane >> 2);
    const int cbase = wn*32 + (lane & 3)*2;
#pragma unroll
    for (int m = 0; m < 4; ++m)
#pragma unroll
        for (int half = 0; half < 2; ++half) {
            const int row = rbase + m*16 + half*8;
#pragma unroll
            for (int n = 0; n < 4; ++n)
                *(float2*)&mydst[row*EPAD + cbase + n*8] =
                    make_float2(c[m][n][half*2], c[m][n][half*2+1]);
        }
    __syncthreads();

    const int t = tid & 255;
    const int row = grp*64 + (t >> 2);
    if (row < rows) {
        const float* h0r = hs + row*EPAD;
        const float* h1r = hs + 128*EPAD + row*EPAD;
        const size_t gbase = (size_t)(rs + row) * IDIM + by*128;
        const int cb = (t & 3) * 4;
#pragma unroll
        for (int j = 0; j < 8; ++j) {
            const int col = cb + j*16;
            float4 a = *(const float4*)(h0r + col);
            float4 b = *(const float4*)(h1r + col);
            float o0 = a.x / (1.0f + expf(-a.x)) * b.x;
            float o1 = a.y / (1.0f + expf(-a.y)) * b.y;
            float o2 = a.z / (1.0f + expf(-a.z)) * b.z;
            float o3 = a.w / (1.0f + expf(-a.w)) * b.w;
            __nv_bfloat162 h01 = __floats2bfloat162_rn(o0, o1);
            __nv_bfloat162 h23 = __floats2bfloat162_rn(o2, o3);
            __nv_bfloat162 l01 = __floats2bfloat162_rn(
                o0 - __bfloat162float(h01.x), o1 - __bfloat162float(h01.y));
            __nv_bfloat162 l23 = __floats2bfloat162_rn(
                o2 - __bfloat162float(h23.x), o3 - __bfloat162float(h23.y));
            *(uint2*)(g_ih + gbase + col) = make_uint2(*(uint32_t*)&h01, *(uint32_t*)&h23);
            *(uint2*)(g_il + gbase + col) = make_uint2(*(uint32_t*)&l01, *(uint32_t*)&l23);
        }
    }
}

// ---------------- GEMM3: op = inter @ wo^T (3-stage, 2 CTAs/SM) -------------
__global__ void __launch_bounds__(256, 2) k_gemm3() {
    extern __shared__ char smem[];
    const int tid = threadIdx.x, lane = tid & 31, wid = tid >> 5;
    const int bx = blockIdx.x, by = blockIdx.y;
    const int rows = g_trows[bx];
    if (rows == 0) return;
    const int rs = g_tstart[bx], e = g_texp[bx];
    const uint32_t sb = s2u(smem);
    const size_t eo = (size_t)e * DIM * IDIM;

    const int r0 = tid >> 2, u0 = tid & 3;
    const int r1 = (tid + 256) >> 2;
    const uint32_t d0 = sw64(r0*64 + u0*16), d1 = sw64(r1*64 + u0*16);
    int ar0 = rs + r0; if (ar0 >= NPAIR) ar0 = NPAIR - 1;
    int ar1 = rs + r1; if (ar1 >= NPAIR) ar1 = NPAIR - 1;
    const size_t a0 = (size_t)ar0*2048 + u0*8, a1 = (size_t)ar1*2048 + u0*8;
    const size_t b0 = (size_t)(by*128 + r0)*2048 + u0*8;
    const size_t b1 = (size_t)(by*128 + r1)*2048 + u0*8;
    const __nv_bfloat16 *Bh = g_woh + eo, *Bl = g_wol + eo;

#define ISSUE3(kt) { uint32_t st = sb + ((kt) % 3)*4*TBS; size_t k0 = (size_t)(kt)*KC; \
        CP16(st         + d0, g_ih + a0 + k0); CP16(st         + d1, g_ih + a1 + k0); \
        CP16(st +   TBS + d0, g_il + a0 + k0); CP16(st +   TBS + d1, g_il + a1 + k0); \
        CP16(st + 2*TBS + d0, Bh   + b0 + k0); CP16(st + 2*TBS + d1, Bh   + b1 + k0); \
        CP16(st + 3*TBS + d0, Bl   + b0 + k0); CP16(st + 3*TBS + d1, Bl   + b1 + k0); }

    const int wm = wid & 1, wn = wid >> 1;
    const uint32_t a_row = wm*64 + (lane & 15);
    const uint32_t a_kb  = ((lane >> 4) & 1) * 16;
    const uint32_t b_row = wn*32 + ((lane >> 4) & 1)*8 + (lane & 7);
    const uint32_t b_k16 = ((lane >> 3) & 1) * 16;

    float c[4][4][4];
#pragma unroll
    for (int m = 0; m < 4; ++m)
#pragma unroll
        for (int n = 0; n < 4; ++n)
#pragma unroll
            for (int q = 0; q < 4; ++q) c[m][n][q] = 0.f;

    ISSUE3(0); CP_COMMIT();
    ISSUE3(1); CP_COMMIT();

    for (int kt = 0; kt < NKT; ++kt) {
        CP_WAITN(1);
        __syncthreads();
        if (kt + 2 < NKT) ISSUE3(kt + 2);
        CP_COMMIT();
        const uint32_t st = sb + (kt % 3)*4*TBS;
#pragma unroll
        for (int kk = 0; kk < 2; ++kk) {
            const uint32_t kb = kk * 32;
            uint32_t fh[4][2], fl[4][2];
#pragma unroll
            for (int p = 0; p < 2; ++p) {
                uint32_t bo = sw64((b_row + p*16)*64 + kb + b_k16);
                LDSM4(fh[2*p][0], fh[2*p][1], fh[2*p+1][0], fh[2*p+1][1], st + 2*TBS + bo);
                LDSM4(fl[2*p][0], fl[2*p][1], fl[2*p+1][0], fl[2*p+1][1], st + 3*TBS + bo);
            }
#pragma unroll
            for (int m = 0; m < 4; ++m) {
                uint32_t ao = sw64((a_row + m*16)*64 + kb + a_kb);
                uint32_t ah[4], al[4];
                LDSM4(ah[0], ah[1], ah[2], ah[3], st + ao);
                LDSM4(al[0], al[1], al[2], al[3], st + TBS + ao);
#pragma unroll
                for (int n = 0; n < 4; ++n) MMA(c[m][n], ah, fh[n]);
#pragma unroll
                for (int n = 0; n < 4; ++n) MMA(c[m][n], ah, fl[n]);
#pragma unroll
                for (int n = 0; n < 4; ++n) MMA(c[m][n], al, fh[n]);
            }
        }
    }
#undef ISSUE3

    const int rbase = wm*64 + (lane >> 2);
    const int cbase = by*128 + wn*32 + (lane & 3)*2;
#pragma unroll
    for (int m = 0; m < 4; ++m)
#pragma unroll
        for (int half = 0; half < 2; ++half) {
            const int rloc = rbase + m*16 + half*8;
            if (rloc >= rows) continue;
            const size_t grow = (size_t)(rs + rloc);
#pragma unroll
            for (int n = 0; n < 4; ++n)
                *(float2*)(g_op + grow*DIM + cbase + n*8) =
                    make_float2(c[m][n][half*2], c[m][n][half*2+1]);
        }
}

// ---------------- combine (+ state reset for next replay) ----------------
__global__ void k_combine(float* __restrict__ out) {
    int t = blockIdx.x;
    float w0 = g_weight[2*t], w1 = g_weight[2*t+1];
    const float4* r0 = (const float4*)(g_op + (size_t)g_pos[2*t]   * DIM);
    const float4* r1 = (const float4*)(g_op + (size_t)g_pos[2*t+1] * DIM);
    float4* o = (float4*)(out + (size_t)t * DIM);
    for (int c = threadIdx.x; c < DIM/4; c += blockDim.x) {
        float4 a = r0[c], b = r1[c];
        o[c] = make_float4(w0*a.x + w1*b.x, w0*a.y + w1*b.y,
                           w0*a.z + w1*b.z, w0*a.w + w1*b.w);
    }
    if (blockIdx.x == 0 && threadIdx.x < NEXP) g_cnt[threadIdx.x] = 0;
    if (blockIdx.x == 0 && threadIdx.x == 0)   g_flag = 0;
}

// ---------------- launch ----------------
extern "C" void kernel_launch(void* const* d_in, const int* in_sizes, int n_in,
                              void* d_out, int out_size) {
    const float* inputs = (const float*)d_in[0];
    const float* logits = (const float*)d_in[1];
    const float* wi0    = (const float*)d_in[2];
    const float* wi1    = (const float*)d_in[3];
    const float* wo     = (const float*)d_in[4];
    float* out = (float*)d_out;

    cudaFuncSetAttribute(k_gemm12, cudaFuncAttributeMaxDynamicSharedMemorySize, SM12);
    cudaFuncSetAttribute(k_gemm3,  cudaFuncAttributeMaxDynamicSharedMemorySize, SM3);

    cudaStream_t s2;
    cudaEvent_t ev0, ev1, ev2;
    cudaStreamCreateWithFlags(&s2, cudaStreamNonBlocking);
    cudaEventCreateWithFlags(&ev0, cudaEventDisableTiming);
    cudaEventCreateWithFlags(&ev1, cudaEventDisableTiming);
    cudaEventCreateWithFlags(&ev2, cudaEventDisableTiming);

    // fork at t=0: side stream converts weights while main stream routes + preps
    cudaEventRecord(ev0, 0);
    cudaStreamWaitEvent(s2, ev0, 0);
    k_convw01<<<dim3(32, 32, 16), 256, 0, s2>>>(wi0, wi1);
    cudaEventRecord(ev1, s2);                  // conv01 done -> gemm12 may start
    k_convwo<<<dim3(32, 32, 8), 256, 0, s2>>>(wo);
    cudaEventRecord(ev2, s2);                  // convwo done -> gemm3 may start

    k_router<<<T_TOK/256, 256>>>(logits);
    k_prep<<<T_TOK, 128>>>(inputs);
    cudaStreamWaitEvent(0, ev1, 0);
    k_gemm12<<<dim3(NTMAX, IDIM/128), 512, SM12>>>();
    cudaStreamWaitEvent(0, ev2, 0);
    k_gemm3 <<<dim3(NTMAX, DIM/128),  256, SM3>>>();
    k_combine<<<T_TOK, 256>>>(out);
}

// round 13
// speedup vs baseline: 1.0002x; 1.0002x over previous
#include <cuda_runtime.h>
#include <cuda_bf16.h>
#include <math.h>
#include <stdint.h>

#define T_TOK 8192
#define DIM   2048
#define IDIM  2048
#define NEXP  8
#define NPAIR 16384
#define NTMAX 136
#define KC    32
#define NKT   64
#define TBS   8192
#define SM12  (4*6*TBS)     // 192 KB
#define SM3   (3*4*TBS)     // 96 KB
#define EPAD  144

// ---------------- device scratch ----------------
__device__ int   g_expert[NPAIR];
__device__ float g_weight[NPAIR];
__device__ int   g_cnt[NEXP], g_cursor[NEXP];
__device__ int   g_pos[NPAIR];
__device__ int   g_pair[NPAIR];          // permuted row -> pair id
__device__ int   g_tstart[NTMAX], g_texp[NTMAX], g_trows[NTMAX];
__device__ int   g_flag;
__device__ __align__(16) __nv_bfloat16 g_xph[(size_t)NPAIR*DIM];
__device__ __align__(16) __nv_bfloat16 g_xpl[(size_t)NPAIR*DIM];
__device__ __align__(16) __nv_bfloat16 g_w0h[(size_t)NEXP*DIM*IDIM];
__device__ __align__(16) __nv_bfloat16 g_w0l[(size_t)NEXP*DIM*IDIM];
__device__ __align__(16) __nv_bfloat16 g_w1h[(size_t)NEXP*DIM*IDIM];
__device__ __align__(16) __nv_bfloat16 g_w1l[(size_t)NEXP*DIM*IDIM];
__device__ __align__(16) __nv_bfloat16 g_woh[(size_t)NEXP*DIM*IDIM];
__device__ __align__(16) __nv_bfloat16 g_wol[(size_t)NEXP*DIM*IDIM];
__device__ __align__(16) __nv_bfloat16 g_ih[(size_t)NPAIR*IDIM];
__device__ __align__(16) __nv_bfloat16 g_il[(size_t)NPAIR*IDIM];

// ---------------- helpers ----------------
__device__ __forceinline__ uint32_t s2u(const void* p) {
    uint32_t a;
    asm("{ .reg .u64 t; cvta.to.shared.u64 t, %1; cvt.u32.u64 %0, t; }" : "=r"(a) : "l"(p));
    return a;
}
__device__ __forceinline__ uint32_t sw64(uint32_t o) { return o ^ ((o >> 3) & 0x30); }

#define CP16(dst, src) asm volatile("cp.async.cg.shared.global [%0], [%1], 16;" \
                                    :: "r"(dst), "l"(src) : "memory")
#define CP_COMMIT() asm volatile("cp.async.commit_group;" ::: "memory")
#define CP_WAITN(n) asm volatile("cp.async.wait_group %0;" :: "n"(n) : "memory")

#define LDSM4(r0,r1,r2,r3,a) asm volatile( \
    "ldmatrix.sync.aligned.m8n8.x4.shared.b16 {%0,%1,%2,%3}, [%4];" \
    : "=r"(r0),"=r"(r1),"=r"(r2),"=r"(r3) : "r"(a))
#define MMA(cc, A, B) asm volatile( \
    "mma.sync.aligned.m16n8k16.row.col.f32.bf16.bf16.f32 " \
    "{%0,%1,%2,%3}, {%4,%5,%6,%7}, {%8,%9}, {%0,%1,%2,%3};" \
    : "+f"(cc[0]),"+f"(cc[1]),"+f"(cc[2]),"+f"(cc[3]) \
    : "r"(A[0]),"r"(A[1]),"r"(A[2]),"r"(A[3]),"r"(B[0]),"r"(B[1]))

// ---------------- zero output (hidden under conv01) ----------------
__global__ void k_zero(float* __restrict__ p) {
    int i = blockIdx.x * blockDim.x + threadIdx.x;
    ((float4*)p)[i] = make_float4(0.f, 0.f, 0.f, 0.f);
}

// ---------------- router ----------------
__global__ void k_router(const float* __restrict__ logits) {
    int t = blockIdx.x * blockDim.x + threadIdx.x;
    const float* l = logits + t * NEXP;
    float v1 = -1e30f, v2 = -1e30f; int i1 = 0, i2 = 0;
#pragma unroll
    for (int e = 0; e < NEXP; ++e) {
        float v = l[e];
        if (v > v1)      { v2 = v1; i2 = i1; v1 = v; i1 = e; }
        else if (v > v2) { v2 = v;  i2 = e; }
    }
    float p = expf(v2 - v1);
    float sden = 1.0f + p;
    float w1 = 1.0f / sden, w2 = p / sden;
    float sn = w1 + w2; w1 /= sn; w2 /= sn;
    g_expert[2*t] = i1; g_expert[2*t+1] = i2;
    g_weight[2*t] = w1; g_weight[2*t+1] = w2;
    atomicAdd(&g_cnt[i1], 1);
    atomicAdd(&g_cnt[i2], 1);
}

// ---------------- weight conversion core: 64x64 tile, transpose + split -----
__device__ __forceinline__ void conv_tile(const float* __restrict__ W,
                                          __nv_bfloat16* __restrict__ Th,
                                          __nv_bfloat16* __restrict__ Tl,
                                          int e, int k0, int n0) {
    __shared__ float s[64][65];
    const float* src = W + (size_t)e * DIM * IDIM;
    const int tx = threadIdx.x & 63, ty = threadIdx.x >> 6;
#pragma unroll
    for (int i = 0; i < 16; ++i) {
        int row = ty + i * 4;
        s[row][tx] = src[(size_t)(k0 + row) * IDIM + n0 + tx];
    }
    __syncthreads();
    const int kp = (threadIdx.x & 31) * 2;
    const int nl = threadIdx.x >> 5;
#pragma unroll
    for (int pass = 0; pass < 8; ++pass) {
        int n_loc = nl + pass * 8;
        float x0 = s[kp][n_loc], x1 = s[kp + 1][n_loc];
        __nv_bfloat162 h = __floats2bfloat162_rn(x0, x1);
        __nv_bfloat162 l = __floats2bfloat162_rn(x0 - __bfloat162float(h.x),
                                                 x1 - __bfloat162float(h.y));
        size_t o = (size_t)e * DIM * IDIM + (size_t)(n0 + n_loc) * DIM + (k0 + kp);
        *(__nv_bfloat162*)(Th + o) = h;
        *(__nv_bfloat162*)(Tl + o) = l;
    }
}

__global__ void k_convw01(const float* __restrict__ W0, const float* __restrict__ W1) {
    int z = blockIdx.z;
    int wsel = z >> 3, e = z & 7;
    conv_tile(wsel ? W1 : W0, wsel ? g_w1h : g_w0h, wsel ? g_w1l : g_w0l,
              e, blockIdx.x * 64, blockIdx.y * 64);
}

__global__ void k_convwo(const float* __restrict__ WO) {
    conv_tile(WO, g_woh, g_wol, blockIdx.z, blockIdx.x * 64, blockIdx.y * 64);
}

// ---------------- prep: schedule + scatter + permute/split (per token) ------
__global__ void k_prep(const float* __restrict__ X) {
    __shared__ int s_d0, s_d1;
    if (blockIdx.x == 0 && threadIdx.x == 0) {
        int off = 0, nt = 0;
        for (int e = 0; e < NEXP; ++e) {
            int c = g_cnt[e];
            g_cursor[e] = off;
            for (int s = 0; s < c; s += 128) {
                g_tstart[nt] = off + s; g_texp[nt] = e;
                g_trows[nt] = (c - s < 128) ? (c - s) : 128; nt++;
            }
            off += c;
        }
        for (int i = nt; i < NTMAX; ++i) g_trows[i] = 0;
        __threadfence();
        atomicExch(&g_flag, 1);
    }
    const int t = blockIdx.x;
    if (threadIdx.x == 0) {
        while (atomicAdd(&g_flag, 0) == 0) {}
        int d0 = atomicAdd(&g_cursor[g_expert[2*t]],   1);
        int d1 = atomicAdd(&g_cursor[g_expert[2*t+1]], 1);
        g_pos[2*t] = d0; g_pos[2*t+1] = d1;
        g_pair[d0] = 2*t; g_pair[d1] = 2*t + 1;
        s_d0 = d0; s_d1 = d1;
    }
    __syncthreads();
    const int d0 = s_d0, d1 = s_d1;
    const float4* src = (const float4*)(X + (size_t)t * DIM);
    __nv_bfloat162* dh0 = (__nv_bfloat162*)(g_xph + (size_t)d0 * DIM);
    __nv_bfloat162* dl0 = (__nv_bfloat162*)(g_xpl + (size_t)d0 * DIM);
    __nv_bfloat162* dh1 = (__nv_bfloat162*)(g_xph + (size_t)d1 * DIM);
    __nv_bfloat162* dl1 = (__nv_bfloat162*)(g_xpl + (size_t)d1 * DIM);
#pragma unroll
    for (int i = 0; i < 4; ++i) {
        int c = threadIdx.x + i * 128;
        float4 v = src[c];
        __nv_bfloat162 h0 = __floats2bfloat162_rn(v.x, v.y);
        __nv_bfloat162 h1 = __floats2bfloat162_rn(v.z, v.w);
        __nv_bfloat162 l0 = __floats2bfloat162_rn(v.x - __bfloat162float(h0.x),
                                                  v.y - __bfloat162float(h0.y));
        __nv_bfloat162 l1 = __floats2bfloat162_rn(v.z - __bfloat162float(h1.x),
                                                  v.w - __bfloat162float(h1.y));
        dh0[2*c] = h0; dh0[2*c+1] = h1;
        dl0[2*c] = l0; dl0[2*c+1] = l1;
        dh1[2*c] = h0; dh1[2*c+1] = h1;
        dl1[2*c] = l0; dl1[2*c+1] = l1;
    }
}

// ---------------- fused GEMM1+2, warp-specialized (512 threads) -------------
__global__ void __launch_bounds__(512, 1) k_gemm12() {
    extern __shared__ char smem[];
    const int tid = threadIdx.x, lane = tid & 31, wid = tid >> 5;
    const int grp = wid >> 3, gid = wid & 7;
    const int bx = blockIdx.x, by = blockIdx.y;
    const int rows = g_trows[bx];
    if (rows == 0) return;
    const int rs = g_tstart[bx], e = g_texp[bx];
    const uint32_t sb = s2u(smem);
    const size_t eo = (size_t)e * DIM * IDIM;

    const int lr = tid >> 2, lu = tid & 3;
    const uint32_t d0 = sw64(lr*64 + lu*16);
    int ar = rs + lr; if (ar >= NPAIR) ar = NPAIR - 1;
    const __nv_bfloat16* pxh = g_xph + (size_t)ar*2048 + lu*8;
    const __nv_bfloat16* pxl = g_xpl + (size_t)ar*2048 + lu*8;
    const size_t bofs = (size_t)(by*128 + lr)*2048 + lu*8;
    const __nv_bfloat16* p0h = g_w0h + eo + bofs;
    const __nv_bfloat16* p0l = g_w0l + eo + bofs;
    const __nv_bfloat16* p1h = g_w1h + eo + bofs;
    const __nv_bfloat16* p1l = g_w1l + eo + bofs;

#define ISSUE12(kt) { uint32_t st = sb + ((kt) & 3)*6*TBS; size_t k0 = (size_t)(kt)*KC; \
        CP16(st         + d0, pxh + k0); CP16(st +   TBS + d0, pxl + k0); \
        CP16(st + 2*TBS + d0, p0h + k0); CP16(st + 3*TBS + d0, p0l + k0); \
        CP16(st + 4*TBS + d0, p1h + k0); CP16(st + 5*TBS + d0, p1l + k0); }

    const int wm = gid & 1, wn = gid >> 1;
    const uint32_t a_row = wm*64 + (lane & 15);
    const uint32_t a_kb  = ((lane >> 4) & 1) * 16;
    const uint32_t b_row = wn*32 + ((lane >> 4) & 1)*8 + (lane & 7);
    const uint32_t b_k16 = ((lane >> 3) & 1) * 16;
    const uint32_t bh_tile = (2 + 2*grp)*TBS;
    const uint32_t bl_tile = (3 + 2*grp)*TBS;

    float c[4][4][4];
#pragma unroll
    for (int m = 0; m < 4; ++m)
#pragma unroll
        for (int n = 0; n < 4; ++n)
#pragma unroll
            for (int q = 0; q < 4; ++q) c[m][n][q] = 0.f;

    ISSUE12(0); CP_COMMIT();
    ISSUE12(1); CP_COMMIT();
    ISSUE12(2); CP_COMMIT();

    for (int kt = 0; kt < NKT; ++kt) {
        CP_WAITN(2);
        __syncthreads();
        if (kt + 3 < NKT) ISSUE12(kt + 3);
        CP_COMMIT();
        const uint32_t st = sb + (kt & 3)*6*TBS;
#pragma unroll
        for (int kk = 0; kk < 2; ++kk) {
            const uint32_t kb = kk * 32;
            uint32_t fh[4][2], fl[4][2];
#pragma unroll
            for (int p = 0; p < 2; ++p) {
                uint32_t bo = sw64((b_row + p*16)*64 + kb + b_k16);
                LDSM4(fh[2*p][0], fh[2*p][1], fh[2*p+1][0], fh[2*p+1][1], st + bh_tile + bo);
                LDSM4(fl[2*p][0], fl[2*p][1], fl[2*p+1][0], fl[2*p+1][1], st + bl_tile + bo);
            }
#pragma unroll
            for (int m = 0; m < 4; ++m) {
                uint32_t ao = sw64((a_row + m*16)*64 + kb + a_kb);
                uint32_t ah[4], al[4];
                LDSM4(ah[0], ah[1], ah[2], ah[3], st + ao);
                LDSM4(al[0], al[1], al[2], al[3], st + TBS + ao);
#pragma unroll
                for (int n = 0; n < 4; ++n) MMA(c[m][n], ah, fh[n]);
#pragma unroll
                for (int n = 0; n < 4; ++n) MMA(c[m][n], ah, fl[n]);
#pragma unroll
                for (int n = 0; n < 4; ++n) MMA(c[m][n], al, fh[n]);
            }
        }
    }
#undef ISSUE12

    __syncthreads();
    float* hs = (float*)smem;
    float* mydst = hs + (size_t)grp * 128 * EPAD;
    const int rbase = wm*64 + (lane >> 2);
    const int cbase = wn*32 + (lane & 3)*2;
#pragma unroll
    for (int m = 0; m < 4; ++m)
#pragma unroll
        for (int half = 0; half < 2; ++half) {
            const int row = rbase + m*16 + half*8;
#pragma unroll
            for (int n = 0; n < 4; ++n)
                *(float2*)&mydst[row*EPAD + cbase + n*8] =
                    make_float2(c[m][n][half*2], c[m][n][half*2+1]);
        }
    __syncthreads();

    const int t = tid & 255;
    const int row = grp*64 + (t >> 2);
    if (row < rows) {
        const float* h0r = hs + row*EPAD;
        const float* h1r = hs + 128*EPAD + row*EPAD;
        const size_t gbase = (size_t)(rs + row) * IDIM + by*128;
        const int cb = (t & 3) * 4;
#pragma unroll
        for (int j = 0; j < 8; ++j) {
            const int col = cb + j*16;
            float4 a = *(const float4*)(h0r + col);
            float4 b = *(const float4*)(h1r + col);
            float o0 = a.x / (1.0f + expf(-a.x)) * b.x;
            float o1 = a.y / (1.0f + expf(-a.y)) * b.y;
            float o2 = a.z / (1.0f + expf(-a.z)) * b.z;
            float o3 = a.w / (1.0f + expf(-a.w)) * b.w;
            __nv_bfloat162 h01 = __floats2bfloat162_rn(o0, o1);
            __nv_bfloat162 h23 = __floats2bfloat162_rn(o2, o3);
            __nv_bfloat162 l01 = __floats2bfloat162_rn(
                o0 - __bfloat162float(h01.x), o1 - __bfloat162float(h01.y));
            __nv_bfloat162 l23 = __floats2bfloat162_rn(
                o2 - __bfloat162float(h23.x), o3 - __bfloat162float(h23.y));
            *(uint2*)(g_ih + gbase + col) = make_uint2(*(uint32_t*)&h01, *(uint32_t*)&h23);
            *(uint2*)(g_il + gbase + col) = make_uint2(*(uint32_t*)&l01, *(uint32_t*)&l23);
        }
    }
}

// ---------------- GEMM3 + fused unpermute/combine ---------------------------
__global__ void __launch_bounds__(256, 2) k_gemm3(float* __restrict__ out) {
    extern __shared__ char smem[];
    const int tid = threadIdx.x, lane = tid & 31, wid = tid >> 5;
    const int bx = blockIdx.x, by = blockIdx.y;
    // per-replay state reset (gemm3 never reads g_cnt/g_flag; runs after prep)
    if (bx == 0 && by == 0 && tid < NEXP) g_cnt[tid] = 0;
    if (bx == 0 && by == 0 && tid == 0)   g_flag = 0;
    const int rows = g_trows[bx];
    if (rows == 0) return;
    const int rs = g_tstart[bx], e = g_texp[bx];
    const uint32_t sb = s2u(smem);
    const size_t eo = (size_t)e * DIM * IDIM;

    const int r0 = tid >> 2, u0 = tid & 3;
    const int r1 = (tid + 256) >> 2;
    const uint32_t d0 = sw64(r0*64 + u0*16), d1 = sw64(r1*64 + u0*16);
    int ar0 = rs + r0; if (ar0 >= NPAIR) ar0 = NPAIR - 1;
    int ar1 = rs + r1; if (ar1 >= NPAIR) ar1 = NPAIR - 1;
    const size_t a0 = (size_t)ar0*2048 + u0*8, a1 = (size_t)ar1*2048 + u0*8;
    const size_t b0 = (size_t)(by*128 + r0)*2048 + u0*8;
    const size_t b1 = (size_t)(by*128 + r1)*2048 + u0*8;
    const __nv_bfloat16 *Bh = g_woh + eo, *Bl = g_wol + eo;

#define ISSUE3(kt) { uint32_t st = sb + ((kt) % 3)*4*TBS; size_t k0 = (size_t)(kt)*KC; \
        CP16(st         + d0, g_ih + a0 + k0); CP16(st         + d1, g_ih + a1 + k0); \
        CP16(st +   TBS + d0, g_il + a0 + k0); CP16(st +   TBS + d1, g_il + a1 + k0); \
        CP16(st + 2*TBS + d0, Bh   + b0 + k0); CP16(st + 2*TBS + d1, Bh   + b1 + k0); \
        CP16(st + 3*TBS + d0, Bl   + b0 + k0); CP16(st + 3*TBS + d1, Bl   + b1 + k0); }

    const int wm = wid & 1, wn = wid >> 1;
    const uint32_t a_row = wm*64 + (lane & 15);
    const uint32_t a_kb  = ((lane >> 4) & 1) * 16;
    const uint32_t b_row = wn*32 + ((lane >> 4) & 1)*8 + (lane & 7);
    const uint32_t b_k16 = ((lane >> 3) & 1) * 16;

    float c[4][4][4];
#pragma unroll
    for (int m = 0; m < 4; ++m)
#pragma unroll
        for (int n = 0; n < 4; ++n)
#pragma unroll
            for (int q = 0; q < 4; ++q) c[m][n][q] = 0.f;

    ISSUE3(0); CP_COMMIT();
    ISSUE3(1); CP_COMMIT();

    for (int kt = 0; kt < NKT; ++kt) {
        CP_WAITN(1);
        __syncthreads();
        if (kt + 2 < NKT) ISSUE3(kt + 2);
        CP_COMMIT();
        const uint32_t st = sb + (kt % 3)*4*TBS;
#pragma unroll
        for (int kk = 0; kk < 2; ++kk) {
            const uint32_t kb = kk * 32;
            uint32_t fh[4][2], fl[4][2];
#pragma unroll
            for (int p = 0; p < 2; ++p) {
                uint32_t bo = sw64((b_row + p*16)*64 + kb + b_k16);
                LDSM4(fh[2*p][0], fh[2*p][1], fh[2*p+1][0], fh[2*p+1][1], st + 2*TBS + bo);
                LDSM4(fl[2*p][0], fl[2*p][1], fl[2*p+1][0], fl[2*p+1][1], st + 3*TBS + bo);
            }
#pragma unroll
            for (int m = 0; m < 4; ++m) {
                uint32_t ao = sw64((a_row + m*16)*64 + kb + a_kb);
                uint32_t ah[4], al[4];
                LDSM4(ah[0], ah[1], ah[2], ah[3], st + ao);
                LDSM4(al[0], al[1], al[2], al[3], st + TBS + ao);
#pragma unroll
                for (int n = 0; n < 4; ++n) MMA(c[m][n], ah, fh[n]);
#pragma unroll
                for (int n = 0; n < 4; ++n) MMA(c[m][n], ah, fl[n]);
#pragma unroll
                for (int n = 0; n < 4; ++n) MMA(c[m][n], al, fh[n]);
            }
        }
    }
#undef ISSUE3

    // fused epilogue: atomicAdd weighted result directly into out.
    // Each out element receives exactly 2 contributions; fp32 add is
    // commutative, so result is bitwise deterministic.
    const int rbase = wm*64 + (lane >> 2);
    const int cbase = by*128 + wn*32 + (lane & 3)*2;
#pragma unroll
    for (int m = 0; m < 4; ++m)
#pragma unroll
        for (int half = 0; half < 2; ++half) {
            const int rloc = rbase + m*16 + half*8;
            if (rloc >= rows) continue;
            const int pr = g_pair[rs + rloc];
            const float w = g_weight[pr];
            float* orow = out + (size_t)(pr >> 1) * DIM + cbase;
#pragma unroll
            for (int n = 0; n < 4; ++n) {
                atomicAdd(orow + n*8,     w * c[m][n][half*2]);
                atomicAdd(orow + n*8 + 1, w * c[m][n][half*2+1]);
            }
        }
}

// ---------------- launch ----------------
extern "C" void kernel_launch(void* const* d_in, const int* in_sizes, int n_in,
                              void* d_out, int out_size) {
    const float* inputs = (const float*)d_in[0];
    const float* logits = (const float*)d_in[1];
    const float* wi0    = (const float*)d_in[2];
    const float* wi1    = (const float*)d_in[3];
    const float* wo     = (const float*)d_in[4];
    float* out = (float*)d_out;

    cudaFuncSetAttribute(k_gemm12, cudaFuncAttributeMaxDynamicSharedMemorySize, SM12);
    cudaFuncSetAttribute(k_gemm3,  cudaFuncAttributeMaxDynamicSharedMemorySize, SM3);

    cudaStream_t s2;
    cudaEvent_t ev0, ev1, ev2;
    cudaStreamCreateWithFlags(&s2, cudaStreamNonBlocking);
    cudaEventCreateWithFlags(&ev0, cudaEventDisableTiming);
    cudaEventCreateWithFlags(&ev1, cudaEventDisableTiming);
    cudaEventCreateWithFlags(&ev2, cudaEventDisableTiming);

    cudaEventRecord(ev0, 0);
    cudaStreamWaitEvent(s2, ev0, 0);
    k_convw01<<<dim3(32, 32, 16), 256, 0, s2>>>(wi0, wi1);
    cudaEventRecord(ev1, s2);                  // conv01 done -> gemm12 may start
    k_convwo<<<dim3(32, 32, 8), 256, 0, s2>>>(wo);
    cudaEventRecord(ev2, s2);                  // convwo done -> gemm3 may start

    k_zero<<<T_TOK*DIM/4/256, 256>>>(out);     // hidden under conv01
    k_router<<<T_TOK/256, 256>>>(logits);
    k_prep<<<T_TOK, 128>>>(inputs);
    cudaStreamWaitEvent(0, ev1, 0);
    k_gemm12<<<dim3(NTMAX, IDIM/128), 512, SM12>>>();
    cudaStreamWaitEvent(0, ev2, 0);
    k_gemm3<<<dim3(NTMAX, DIM/128), 256, SM3>>>(out);
}